// round 1
// baseline (speedup 1.0000x reference)
#include <cuda_runtime.h>
#include <cstdint>

#define E_TILE   64
#define THREADS  512
#define F_DIM    32
#define H_DIM    128
#define IN_DIM   321
#define K1PAD    336     // 321 padded to multiple of 16
#define HID      512
#define OUT_DIM  256
#define XLD      340     // 336 + 4 pad -> conflict-friendly bank stride (20 mod 32)
#define HLD      516     // 512 + 4 pad -> bank stride 4 mod 32 (conflict-free A-frag)

// tf32-rounded weights (padded W1), written by prologue kernel each launch.
__device__ __align__(16) float g_W1t[K1PAD * HID];
__device__ __align__(16) float g_W2t[HID * HID];
__device__ __align__(16) float g_W3t[HID * OUT_DIM];

__device__ __forceinline__ float tf32r(float x) {
    unsigned u;
    asm("cvt.rna.tf32.f32 %0, %1;" : "=r"(u) : "f"(x));
    return __uint_as_float(u);
}

__global__ void convert_weights_kernel(const float* __restrict__ W1,
                                       const float* __restrict__ W2,
                                       const float* __restrict__ W3) {
    int i = blockIdx.x * blockDim.x + threadIdx.x;
    const int n1 = K1PAD * HID, n2 = HID * HID, n3 = HID * OUT_DIM;
    if (i < n1) {
        int r = i / HID, c = i % HID;
        g_W1t[i] = (r < IN_DIM) ? tf32r(W1[r * HID + c]) : 0.f;
        return;
    }
    i -= n1;
    if (i < n2) { g_W2t[i] = tf32r(W2[i]); return; }
    i -= n2;
    if (i < n3) { g_W3t[i] = tf32r(W3[i]); }
}

// ---------------- cp.async helpers ----------------
__device__ __forceinline__ void cp16(uint32_t saddr, const void* gptr) {
    asm volatile("cp.async.ca.shared.global [%0], [%1], 16;" :: "r"(saddr), "l"(gptr));
}
__device__ __forceinline__ void cp_commit() { asm volatile("cp.async.commit_group;"); }
template <int N> __device__ __forceinline__ void cp_wait() {
    asm volatile("cp.async.wait_group %0;" :: "n"(N));
}

__device__ __forceinline__ void mma_tf32(float c[4], const uint32_t a[4],
                                         uint32_t b0, uint32_t b1) {
    asm volatile(
        "mma.sync.aligned.m16n8k8.row.col.f32.tf32.tf32.f32 "
        "{%0,%1,%2,%3}, {%4,%5,%6,%7}, {%8,%9}, {%0,%1,%2,%3};"
        : "+f"(c[0]), "+f"(c[1]), "+f"(c[2]), "+f"(c[3])
        : "r"(a[0]), "r"(a[1]), "r"(a[2]), "r"(a[3]), "r"(b0), "r"(b1));
}

// One fused GEMM: [64, K] (smem, tf32) x [K, N] (global tf32, staged) -> acc regs.
// Warp grid 2(M) x 8(N). NT = n8-tiles per warp (8 -> N=512, 4 -> N=256).
template <int N, int NT, int NSTG>
__device__ __forceinline__ void run_gemm(const float* __restrict__ Wg,
                                         const float* __restrict__ As, int lda,
                                         float* Bst, float (&acc)[2][8][4],
                                         int wm, int wn, int g, int tig, int tid) {
    constexpr int BLD = N + 8;
    constexpr int CP_ITERS = (16 * N / 4) / THREADS;  // float4 per thread per stage
    uint32_t bst_base = (uint32_t)__cvta_generic_to_shared(Bst);

#pragma unroll
    for (int mt = 0; mt < 2; mt++)
#pragma unroll
        for (int nt = 0; nt < NT; nt++)
#pragma unroll
            for (int r = 0; r < 4; r++) acc[mt][nt][r] = 0.f;

    auto stage_cp = [&](int s, int buf) {
#pragma unroll
        for (int it = 0; it < CP_ITERS; it++) {
            int idx = it * THREADS + tid;           // float4 index within stage
            int r = idx / (N / 4);
            int c = idx % (N / 4);
            uint32_t dst = bst_base + (uint32_t)((buf * 16 + r) * BLD + c * 4) * 4u;
            cp16(dst, Wg + (size_t)(s * 16 + r) * N + c * 4);
        }
        cp_commit();
    };

    stage_cp(0, 0);
    for (int s = 0; s < NSTG; s++) {
        if (s + 1 < NSTG) { stage_cp(s + 1, (s + 1) & 1); cp_wait<1>(); }
        else              { cp_wait<0>(); }
        __syncthreads();
        const float* B = Bst + (s & 1) * 16 * BLD;
#pragma unroll
        for (int k8 = 0; k8 < 2; k8++) {
            int kg = s * 16 + k8 * 8;
            uint32_t a[2][4];
#pragma unroll
            for (int mt = 0; mt < 2; mt++) {
                const float* ar = As + (wm * 32 + mt * 16 + g) * lda + kg + tig;
                a[mt][0] = __float_as_uint(ar[0]);
                a[mt][1] = __float_as_uint(ar[8 * lda]);
                a[mt][2] = __float_as_uint(ar[4]);
                a[mt][3] = __float_as_uint(ar[8 * lda + 4]);
            }
#pragma unroll
            for (int nt = 0; nt < NT; nt++) {
                int col = wn * (NT * 8) + nt * 8 + g;
                uint32_t b0 = __float_as_uint(B[(k8 * 8 + tig) * BLD + col]);
                uint32_t b1 = __float_as_uint(B[(k8 * 8 + tig + 4) * BLD + col]);
                mma_tf32(acc[0][nt], a[0], b0, b1);
                mma_tf32(acc[1][nt], a[1], b0, b1);
            }
        }
        __syncthreads();  // buffer (s&1) now reusable next iteration
    }
}

__global__ void __launch_bounds__(THREADS, 1)
edge_mlp_kernel(const float* __restrict__ nf, const float* __restrict__ nh,
                const int* __restrict__ src_idx, const int* __restrict__ dst_idx,
                const float* __restrict__ dist,
                const float* __restrict__ b1, const float* __restrict__ b2,
                const float* __restrict__ b3,
                float* __restrict__ out, int E) {
    extern __shared__ float smem[];
    float* Xs = smem;                   // [64][XLD]
    float* Hs = smem + E_TILE * XLD;    // [64][HLD]

    int tid = threadIdx.x;
    int wid = tid >> 5;
    int lane = tid & 31;
    int g = lane >> 2, tig = lane & 3;
    int wm = wid >> 3, wn = wid & 7;    // 2 x 8 warp grid
    int e0 = blockIdx.x * E_TILE;

    // ---- gather: x = [dst_feat(32) | dst_hid(128) | src_feat(32) | dst_hid(128) | dist | 0pad] ----
    {
        int ebase = wid * 4;  // 4 edges per warp
#pragma unroll
        for (int q = 0; q < 4; q++) {
            int ee = ebase + q;
            int edge = e0 + ee;
            int d  = (edge < E) ? dst_idx[edge] : 0;
            int sn = (edge < E) ? src_idx[edge] : 0;
            float* xr = Xs + ee * XLD;
            xr[lane]       = tf32r(nf[(size_t)d * F_DIM + lane]);
            xr[160 + lane] = tf32r(nf[(size_t)sn * F_DIM + lane]);
#pragma unroll
            for (int j = 0; j < 4; j++) {
                float v = tf32r(nh[(size_t)d * H_DIM + j * 32 + lane]);
                xr[32  + j * 32 + lane] = v;
                xr[192 + j * 32 + lane] = v;
            }
            if (lane < 16)
                xr[320 + lane] = (lane == 0) ? tf32r((edge < E) ? dist[edge] : 0.f) : 0.f;
        }
    }
    __syncthreads();

    float acc[2][8][4];

    // ---- layer 1: Xs[64,336] @ W1t[336,512] -> Hs (B staged in free Hs region) ----
    run_gemm<HID, 8, K1PAD / 16>(g_W1t, Xs, XLD, Hs, acc, wm, wn, g, tig, tid);
#pragma unroll
    for (int mt = 0; mt < 2; mt++)
#pragma unroll
        for (int nt = 0; nt < 8; nt++) {
            int col = wn * 64 + nt * 8 + 2 * tig;
            float bb0 = __ldg(&b1[col]), bb1 = __ldg(&b1[col + 1]);
            int r0 = wm * 32 + mt * 16 + g;
            Hs[r0 * HLD + col]           = tf32r(fmaxf(acc[mt][nt][0] + bb0, 0.f));
            Hs[r0 * HLD + col + 1]       = tf32r(fmaxf(acc[mt][nt][1] + bb1, 0.f));
            Hs[(r0 + 8) * HLD + col]     = tf32r(fmaxf(acc[mt][nt][2] + bb0, 0.f));
            Hs[(r0 + 8) * HLD + col + 1] = tf32r(fmaxf(acc[mt][nt][3] + bb1, 0.f));
        }
    __syncthreads();

    // ---- layer 2: Hs @ W2t[512,512] -> Hs (B staged in Xs region) ----
    run_gemm<HID, 8, HID / 16>(g_W2t, Hs, HLD, Xs, acc, wm, wn, g, tig, tid);
#pragma unroll
    for (int mt = 0; mt < 2; mt++)
#pragma unroll
        for (int nt = 0; nt < 8; nt++) {
            int col = wn * 64 + nt * 8 + 2 * tig;
            float bb0 = __ldg(&b2[col]), bb1 = __ldg(&b2[col + 1]);
            int r0 = wm * 32 + mt * 16 + g;
            Hs[r0 * HLD + col]           = tf32r(fmaxf(acc[mt][nt][0] + bb0, 0.f));
            Hs[r0 * HLD + col + 1]       = tf32r(fmaxf(acc[mt][nt][1] + bb1, 0.f));
            Hs[(r0 + 8) * HLD + col]     = tf32r(fmaxf(acc[mt][nt][2] + bb0, 0.f));
            Hs[(r0 + 8) * HLD + col + 1] = tf32r(fmaxf(acc[mt][nt][3] + bb1, 0.f));
        }
    __syncthreads();

    // ---- layer 3: Hs @ W3t[512,256] -> out (B staged in Xs region) ----
    run_gemm<OUT_DIM, 4, HID / 16>(g_W3t, Hs, HLD, Xs, acc, wm, wn, g, tig, tid);
#pragma unroll
    for (int mt = 0; mt < 2; mt++)
#pragma unroll
        for (int nt = 0; nt < 4; nt++) {
            int col = wn * 32 + nt * 8 + 2 * tig;
            float bb0 = __ldg(&b3[col]), bb1 = __ldg(&b3[col + 1]);
            int r0 = wm * 32 + mt * 16 + g;
            int edge0 = e0 + r0;
            if (edge0 < E) {
                float2 v = make_float2(acc[mt][nt][0] + bb0, acc[mt][nt][1] + bb1);
                *reinterpret_cast<float2*>(&out[(size_t)edge0 * OUT_DIM + col]) = v;
            }
            int edge1 = e0 + r0 + 8;
            if (edge1 < E) {
                float2 v = make_float2(acc[mt][nt][2] + bb0, acc[mt][nt][3] + bb1);
                *reinterpret_cast<float2*>(&out[(size_t)edge1 * OUT_DIM + col]) = v;
            }
        }
}

extern "C" void kernel_launch(void* const* d_in, const int* in_sizes, int n_in,
                              void* d_out, int out_size) {
    const float* nf   = (const float*)d_in[0];
    const float* nh   = (const float*)d_in[1];
    const int*   srci = (const int*)d_in[2];
    const int*   dsti = (const int*)d_in[3];
    const float* dist = (const float*)d_in[4];
    const float* W1   = (const float*)d_in[5];
    const float* b1   = (const float*)d_in[6];
    const float* W2   = (const float*)d_in[7];
    const float* b2   = (const float*)d_in[8];
    const float* W3   = (const float*)d_in[9];
    const float* b3   = (const float*)d_in[10];
    float* out = (float*)d_out;

    int E = in_sizes[2];

    const int total_w = K1PAD * HID + HID * HID + HID * OUT_DIM;
    convert_weights_kernel<<<(total_w + 511) / 512, 512>>>(W1, W2, W3);

    const int smem_bytes = (E_TILE * XLD + E_TILE * HLD) * (int)sizeof(float);
    cudaFuncSetAttribute(edge_mlp_kernel,
                         cudaFuncAttributeMaxDynamicSharedMemorySize, smem_bytes);

    int grid = (E + E_TILE - 1) / E_TILE;
    edge_mlp_kernel<<<grid, THREADS, smem_bytes>>>(nf, nh, srci, dsti, dist,
                                                   b1, b2, b3, out, E);
}

// round 2
// speedup vs baseline: 1.0010x; 1.0010x over previous
#include <cuda_runtime.h>
#include <cstdint>

#define E_TILE   64
#define THREADS  512
#define F_DIM    32
#define H_DIM    128
#define IN_DIM   321
#define K1PAD    336     // 321 padded to multiple of 16
#define HID      512
#define OUT_DIM  256
#define XLD      340     // 336 + 4 pad -> conflict-friendly bank stride (20 mod 32)
#define HLD      516     // 512 + 4 pad -> bank stride 4 mod 32 (conflict-free A-frag)

// tf32-rounded weights (padded W1), written by prologue kernel each launch.
__device__ __align__(16) float g_W1t[K1PAD * HID];
__device__ __align__(16) float g_W2t[HID * HID];
__device__ __align__(16) float g_W3t[HID * OUT_DIM];

__device__ __forceinline__ float tf32r(float x) {
    unsigned u;
    asm("cvt.rna.tf32.f32 %0, %1;" : "=r"(u) : "f"(x));
    return __uint_as_float(u);
}

__global__ void convert_weights_kernel(const float* __restrict__ W1,
                                       const float* __restrict__ W2,
                                       const float* __restrict__ W3) {
    int i = blockIdx.x * blockDim.x + threadIdx.x;
    const int n1 = K1PAD * HID, n2 = HID * HID, n3 = HID * OUT_DIM;
    if (i < n1) {
        int r = i / HID, c = i % HID;
        g_W1t[i] = (r < IN_DIM) ? tf32r(W1[r * HID + c]) : 0.f;
        return;
    }
    i -= n1;
    if (i < n2) { g_W2t[i] = tf32r(W2[i]); return; }
    i -= n2;
    if (i < n3) { g_W3t[i] = tf32r(W3[i]); }
}

// ---------------- cp.async helpers ----------------
__device__ __forceinline__ void cp16(uint32_t saddr, const void* gptr) {
    asm volatile("cp.async.ca.shared.global [%0], [%1], 16;" :: "r"(saddr), "l"(gptr));
}
__device__ __forceinline__ void cp_commit() { asm volatile("cp.async.commit_group;"); }
template <int N> __device__ __forceinline__ void cp_wait() {
    asm volatile("cp.async.wait_group %0;" :: "n"(N));
}

__device__ __forceinline__ void mma_tf32(float c[4], const uint32_t a[4],
                                         uint32_t b0, uint32_t b1) {
    asm volatile(
        "mma.sync.aligned.m16n8k8.row.col.f32.tf32.tf32.f32 "
        "{%0,%1,%2,%3}, {%4,%5,%6,%7}, {%8,%9}, {%0,%1,%2,%3};"
        : "+f"(c[0]), "+f"(c[1]), "+f"(c[2]), "+f"(c[3])
        : "r"(a[0]), "r"(a[1]), "r"(a[2]), "r"(a[3]), "r"(b0), "r"(b1));
}

// One fused GEMM: [64, K] (smem, tf32) x [K, N] (global tf32, staged) -> acc regs.
// Warp grid 2(M) x 8(N). NT = n8-tiles per warp (8 -> N=512, 4 -> N=256).
template <int N, int NT, int NSTG>
__device__ __forceinline__ void run_gemm(const float* __restrict__ Wg,
                                         const float* __restrict__ As, int lda,
                                         float* Bst, float (&acc)[2][8][4],
                                         int wm, int wn, int g, int tig, int tid) {
    constexpr int BLD = N + 8;
    constexpr int CP_ITERS = (16 * N / 4) / THREADS;  // float4 per thread per stage
    uint32_t bst_base = (uint32_t)__cvta_generic_to_shared(Bst);

#pragma unroll
    for (int mt = 0; mt < 2; mt++)
#pragma unroll
        for (int nt = 0; nt < NT; nt++)
#pragma unroll
            for (int r = 0; r < 4; r++) acc[mt][nt][r] = 0.f;

    auto stage_cp = [&](int s, int buf) {
#pragma unroll
        for (int it = 0; it < CP_ITERS; it++) {
            int idx = it * THREADS + tid;           // float4 index within stage
            int r = idx / (N / 4);
            int c = idx % (N / 4);
            uint32_t dst = bst_base + (uint32_t)((buf * 16 + r) * BLD + c * 4) * 4u;
            cp16(dst, Wg + (size_t)(s * 16 + r) * N + c * 4);
        }
        cp_commit();
    };

    stage_cp(0, 0);
    for (int s = 0; s < NSTG; s++) {
        if (s + 1 < NSTG) { stage_cp(s + 1, (s + 1) & 1); cp_wait<1>(); }
        else              { cp_wait<0>(); }
        __syncthreads();
        const float* B = Bst + (s & 1) * 16 * BLD;
#pragma unroll
        for (int k8 = 0; k8 < 2; k8++) {
            int kg = s * 16 + k8 * 8;
            uint32_t a[2][4];
#pragma unroll
            for (int mt = 0; mt < 2; mt++) {
                const float* ar = As + (wm * 32 + mt * 16 + g) * lda + kg + tig;
                a[mt][0] = __float_as_uint(ar[0]);
                a[mt][1] = __float_as_uint(ar[8 * lda]);
                a[mt][2] = __float_as_uint(ar[4]);
                a[mt][3] = __float_as_uint(ar[8 * lda + 4]);
            }
#pragma unroll
            for (int nt = 0; nt < NT; nt++) {
                int col = wn * (NT * 8) + nt * 8 + g;
                uint32_t b0 = __float_as_uint(B[(k8 * 8 + tig) * BLD + col]);
                uint32_t b1 = __float_as_uint(B[(k8 * 8 + tig + 4) * BLD + col]);
                mma_tf32(acc[0][nt], a[0], b0, b1);
                mma_tf32(acc[1][nt], a[1], b0, b1);
            }
        }
        __syncthreads();  // buffer (s&1) now reusable next iteration
    }
}

__global__ void __launch_bounds__(THREADS, 1)
edge_mlp_kernel(const float* __restrict__ nf, const float* __restrict__ nh,
                const int* __restrict__ src_idx, const int* __restrict__ dst_idx,
                const float* __restrict__ dist,
                const float* __restrict__ b1, const float* __restrict__ b2,
                const float* __restrict__ b3,
                float* __restrict__ out, int E) {
    extern __shared__ float smem[];
    float* Xs = smem;                   // [64][XLD]
    float* Hs = smem + E_TILE * XLD;    // [64][HLD]

    int tid = threadIdx.x;
    int wid = tid >> 5;
    int lane = tid & 31;
    int g = lane >> 2, tig = lane & 3;
    int wm = wid >> 3, wn = wid & 7;    // 2 x 8 warp grid
    int e0 = blockIdx.x * E_TILE;

    // ---- gather: x = [dst_feat(32) | dst_hid(128) | src_feat(32) | dst_hid(128) | dist | 0pad] ----
    {
        int ebase = wid * 4;  // 4 edges per warp
#pragma unroll
        for (int q = 0; q < 4; q++) {
            int ee = ebase + q;
            int edge = e0 + ee;
            int d  = (edge < E) ? dst_idx[edge] : 0;
            int sn = (edge < E) ? src_idx[edge] : 0;
            float* xr = Xs + ee * XLD;
            xr[lane]       = tf32r(nf[(size_t)d * F_DIM + lane]);
            xr[160 + lane] = tf32r(nf[(size_t)sn * F_DIM + lane]);
#pragma unroll
            for (int j = 0; j < 4; j++) {
                float v = tf32r(nh[(size_t)d * H_DIM + j * 32 + lane]);
                xr[32  + j * 32 + lane] = v;
                xr[192 + j * 32 + lane] = v;
            }
            if (lane < 16)
                xr[320 + lane] = (lane == 0) ? tf32r((edge < E) ? dist[edge] : 0.f) : 0.f;
        }
    }
    __syncthreads();

    float acc[2][8][4];

    // ---- layer 1: Xs[64,336] @ W1t[336,512] -> Hs (B staged in free Hs region) ----
    run_gemm<HID, 8, K1PAD / 16>(g_W1t, Xs, XLD, Hs, acc, wm, wn, g, tig, tid);
#pragma unroll
    for (int mt = 0; mt < 2; mt++)
#pragma unroll
        for (int nt = 0; nt < 8; nt++) {
            int col = wn * 64 + nt * 8 + 2 * tig;
            float bb0 = __ldg(&b1[col]), bb1 = __ldg(&b1[col + 1]);
            int r0 = wm * 32 + mt * 16 + g;
            Hs[r0 * HLD + col]           = tf32r(fmaxf(acc[mt][nt][0] + bb0, 0.f));
            Hs[r0 * HLD + col + 1]       = tf32r(fmaxf(acc[mt][nt][1] + bb1, 0.f));
            Hs[(r0 + 8) * HLD + col]     = tf32r(fmaxf(acc[mt][nt][2] + bb0, 0.f));
            Hs[(r0 + 8) * HLD + col + 1] = tf32r(fmaxf(acc[mt][nt][3] + bb1, 0.f));
        }
    __syncthreads();

    // ---- layer 2: Hs @ W2t[512,512] -> Hs (B staged in Xs region) ----
    run_gemm<HID, 8, HID / 16>(g_W2t, Hs, HLD, Xs, acc, wm, wn, g, tig, tid);
#pragma unroll
    for (int mt = 0; mt < 2; mt++)
#pragma unroll
        for (int nt = 0; nt < 8; nt++) {
            int col = wn * 64 + nt * 8 + 2 * tig;
            float bb0 = __ldg(&b2[col]), bb1 = __ldg(&b2[col + 1]);
            int r0 = wm * 32 + mt * 16 + g;
            Hs[r0 * HLD + col]           = tf32r(fmaxf(acc[mt][nt][0] + bb0, 0.f));
            Hs[r0 * HLD + col + 1]       = tf32r(fmaxf(acc[mt][nt][1] + bb1, 0.f));
            Hs[(r0 + 8) * HLD + col]     = tf32r(fmaxf(acc[mt][nt][2] + bb0, 0.f));
            Hs[(r0 + 8) * HLD + col + 1] = tf32r(fmaxf(acc[mt][nt][3] + bb1, 0.f));
        }
    __syncthreads();

    // ---- layer 3: Hs @ W3t[512,256] -> out (B staged in Xs region) ----
    run_gemm<OUT_DIM, 4, HID / 16>(g_W3t, Hs, HLD, Xs, acc, wm, wn, g, tig, tid);
#pragma unroll
    for (int mt = 0; mt < 2; mt++)
#pragma unroll
        for (int nt = 0; nt < 4; nt++) {
            int col = wn * 32 + nt * 8 + 2 * tig;
            float bb0 = __ldg(&b3[col]), bb1 = __ldg(&b3[col + 1]);
            int r0 = wm * 32 + mt * 16 + g;
            int edge0 = e0 + r0;
            if (edge0 < E) {
                float2 v = make_float2(acc[mt][nt][0] + bb0, acc[mt][nt][1] + bb1);
                *reinterpret_cast<float2*>(&out[(size_t)edge0 * OUT_DIM + col]) = v;
            }
            int edge1 = e0 + r0 + 8;
            if (edge1 < E) {
                float2 v = make_float2(acc[mt][nt][2] + bb0, acc[mt][nt][3] + bb1);
                *reinterpret_cast<float2*>(&out[(size_t)edge1 * OUT_DIM + col]) = v;
            }
        }
}

extern "C" void kernel_launch(void* const* d_in, const int* in_sizes, int n_in,
                              void* d_out, int out_size) {
    const float* nf   = (const float*)d_in[0];
    const float* nh   = (const float*)d_in[1];
    const int*   srci = (const int*)d_in[2];
    const int*   dsti = (const int*)d_in[3];
    const float* dist = (const float*)d_in[4];
    const float* W1   = (const float*)d_in[5];
    const float* b1   = (const float*)d_in[6];
    const float* W2   = (const float*)d_in[7];
    const float* b2   = (const float*)d_in[8];
    const float* W3   = (const float*)d_in[9];
    const float* b3   = (const float*)d_in[10];
    float* out = (float*)d_out;

    int E = in_sizes[2];

    const int total_w = K1PAD * HID + HID * HID + HID * OUT_DIM;
    convert_weights_kernel<<<(total_w + 511) / 512, 512>>>(W1, W2, W3);

    const int smem_bytes = (E_TILE * XLD + E_TILE * HLD) * (int)sizeof(float);
    cudaFuncSetAttribute(edge_mlp_kernel,
                         cudaFuncAttributeMaxDynamicSharedMemorySize, smem_bytes);

    int grid = (E + E_TILE - 1) / E_TILE;
    edge_mlp_kernel<<<grid, THREADS, smem_bytes>>>(nf, nh, srci, dsti, dist,
                                                   b1, b2, b3, out, E);
}